// round 4
// baseline (speedup 1.0000x reference)
#include <cuda_runtime.h>

#define N_ 8
#define C_ 128
#define H_ 64
#define W_ 64
#define HW 4096

typedef unsigned long long u64;

// scratch (no allocs allowed)
__device__ float g_t7 [N_ * C_ * HW];            // 16 MB
__device__ float g_y  [N_ * C_ * HW];            // 16 MB
__device__ float g_up [N_ * 32 * C_ * C_];       // 16 MB split-K partials
__device__ float g_u  [N_ * C_ * C_];            // 512 KB (transposed: [n][ci][co])
__device__ float g_p7t[C_ * C_];                 // p7 transposed [k][co]

// ---- f32x2 helpers -------------------------------------------------------
__device__ __forceinline__ u64 pack2(float a, float b) {
    u64 r;
    asm("mov.b64 %0, {%1, %2};" : "=l"(r) : "f"(a), "f"(b));
    return r;
}
__device__ __forceinline__ void fma2(u64& d, u64 a, u64 b) {
    asm("fma.rn.f32x2 %0, %1, %2, %0;" : "+l"(d) : "l"(a), "l"(b));
}
__device__ __forceinline__ float lo2(u64 v) { return __uint_as_float((unsigned)v); }
__device__ __forceinline__ float hi2(u64 v) { return __uint_as_float((unsigned)(v >> 32)); }

// ---------------------------------------------------------------------------
// K0: transpose p7 -> g_p7t[k][co]
// ---------------------------------------------------------------------------
__global__ void k0_tr(const float* __restrict__ p7)
{
    int idx = blockIdx.x * 256 + threadIdx.x;   // 16384
    int kk = idx >> 7, co = idx & 127;
    g_p7t[idx] = p7[co * 128 + kk];
}

// ---------------------------------------------------------------------------
// K1: t7[n,co,row,:] = sum_c p7[co,c] * relu(x[n,c,row,:])
// 128 threads: ty(16) x 8 co-pairs(co paired via f32x2), tx(8) x 8 w
// ---------------------------------------------------------------------------
__global__ void k1_t7(const float* __restrict__ x)
{
    __shared__ __align__(16) float xs [128 * 64];   // relu(x)[ci][w]
    __shared__ __align__(16) float as2[16 * 128];   // p7t chunk [kk][co]
    const int row = blockIdx.x, n = blockIdx.y;
    const int t = threadIdx.x;
    const int tx = t & 7, ty = t >> 3;
    const float* xn = x + (size_t)n * C_ * HW + row * 64;

    for (int r = 0; r < 64; r++) {
        int idx = r * 128 + t;
        int ci = idx >> 6, w = idx & 63;
        xs[idx] = fmaxf(xn[(size_t)ci * HW + w], 0.f);
    }

    u64 acc[4][8];
#pragma unroll
    for (int p = 0; p < 4; p++)
#pragma unroll
        for (int j = 0; j < 8; j++) acc[p][j] = 0ull;

    for (int kb = 0; kb < 8; kb++) {
        __syncthreads();
#pragma unroll
        for (int r = 0; r < 16; r++)
            as2[r * 128 + t] = g_p7t[kb * 2048 + r * 128 + t];
        __syncthreads();
#pragma unroll
        for (int kk = 0; kk < 16; kk++) {
            int k = kb * 16 + kk;
            float4 b0 = *reinterpret_cast<const float4*>(&xs[k * 64 + tx * 8]);
            float4 b1 = *reinterpret_cast<const float4*>(&xs[k * 64 + tx * 8 + 4]);
            u64 a0 = *reinterpret_cast<const u64*>(&as2[kk * 128 + ty * 8 + 0]);
            u64 a1 = *reinterpret_cast<const u64*>(&as2[kk * 128 + ty * 8 + 2]);
            u64 a2 = *reinterpret_cast<const u64*>(&as2[kk * 128 + ty * 8 + 4]);
            u64 a3 = *reinterpret_cast<const u64*>(&as2[kk * 128 + ty * 8 + 6]);
            u64 bb[8];
            bb[0] = pack2(b0.x, b0.x); bb[1] = pack2(b0.y, b0.y);
            bb[2] = pack2(b0.z, b0.z); bb[3] = pack2(b0.w, b0.w);
            bb[4] = pack2(b1.x, b1.x); bb[5] = pack2(b1.y, b1.y);
            bb[6] = pack2(b1.z, b1.z); bb[7] = pack2(b1.w, b1.w);
#pragma unroll
            for (int j = 0; j < 8; j++) {
                fma2(acc[0][j], a0, bb[j]);
                fma2(acc[1][j], a1, bb[j]);
                fma2(acc[2][j], a2, bb[j]);
                fma2(acc[3][j], a3, bb[j]);
            }
        }
    }

    float* t7n = g_t7 + (size_t)n * C_ * HW + row * 64;
#pragma unroll
    for (int p = 0; p < 4; p++) {
        int co0 = ty * 8 + 2 * p;
#pragma unroll
        for (int jq = 0; jq < 2; jq++) {
            float4 vl = make_float4(lo2(acc[p][jq*4+0]), lo2(acc[p][jq*4+1]),
                                    lo2(acc[p][jq*4+2]), lo2(acc[p][jq*4+3]));
            float4 vh = make_float4(hi2(acc[p][jq*4+0]), hi2(acc[p][jq*4+1]),
                                    hi2(acc[p][jq*4+2]), hi2(acc[p][jq*4+3]));
            *reinterpret_cast<float4*>(&t7n[(size_t)co0 * HW + tx * 8 + jq * 4]) = vl;
            *reinterpret_cast<float4*>(&t7n[(size_t)(co0 + 1) * HW + tx * 8 + jq * 4]) = vh;
        }
    }
}

// ---------------------------------------------------------------------------
// K2: grouped 3x7 conv, f32x2 along cin.
// 128 threads = 32 w-lanes x 4 cin-octs; thread: 8 cin (4 pairs) x 8 h.
// ---------------------------------------------------------------------------
__global__ void k2_conv(const float* __restrict__ x, const float* __restrict__ p10)
{
    __shared__ __align__(16) float xs[8 * 10 * 38];   // [ci][hh][ww]  3040
    __shared__ __align__(16) float ws[8 * 21 * 32];   // [ci][k][cin]  5376
    const int tile = blockIdx.x;        // 0..15
    const int g = blockIdx.y, n = blockIdx.z;
    const int h0 = (tile >> 1) * 8, w0 = (tile & 1) * 32;
    const int t = threadIdx.x;          // 128
    const int wl = t & 31, oct = t >> 5;

    u64 acc[4][8];
#pragma unroll
    for (int q = 0; q < 4; q++)
#pragma unroll
        for (int hh = 0; hh < 8; hh++) acc[q][hh] = 0ull;

    for (int cc = 0; cc < 4; cc++) {
        __syncthreads();
        for (int idx = t; idx < 3040; idx += 128) {
            int ci = idx / 380;
            int rem = idx - ci * 380;
            int hh = rem / 38, ww = rem - hh * 38;
            int hg = h0 - 1 + hh, wg = w0 - 3 + ww;
            float v = 0.f;
            if ((unsigned)hg < 64u && (unsigned)wg < 64u)
                v = x[(((size_t)n * C_ + g * 32 + cc * 8 + ci) * 64 + hg) * 64 + wg];
            xs[idx] = v;
        }
        for (int idx = t; idx < 5376; idx += 128) {
            int ci = idx / 672;
            int rem = idx - ci * 672;
            ws[idx] = p10[(size_t)(g * 32 + cc * 8 + ci) * 672 + rem];
        }
        __syncthreads();

#pragma unroll 1
        for (int ci = 0; ci < 8; ci++) {
#pragma unroll
            for (int k = 0; k < 21; k++) {
                const int di = k / 7, dj = k - di * 7;
                const float* wp = &ws[(ci * 21 + k) * 32 + oct * 8];
                u64 w0p = *reinterpret_cast<const u64*>(wp + 0);
                u64 w1p = *reinterpret_cast<const u64*>(wp + 2);
                u64 w2p = *reinterpret_cast<const u64*>(wp + 4);
                u64 w3p = *reinterpret_cast<const u64*>(wp + 6);
                const float* xr = &xs[(ci * 10 + di) * 38 + wl + dj];
#pragma unroll
                for (int hh = 0; hh < 8; hh++) {
                    float xv = xr[hh * 38];
                    u64 xx = pack2(xv, xv);
                    fma2(acc[0][hh], w0p, xx);
                    fma2(acc[1][hh], w1p, xx);
                    fma2(acc[2][hh], w2p, xx);
                    fma2(acc[3][hh], w3p, xx);
                }
            }
        }
    }

#pragma unroll
    for (int q = 0; q < 4; q++)
#pragma unroll
        for (int hh = 0; hh < 8; hh++) {
            int cin0 = g * 32 + oct * 8 + 2 * q;
            g_y[(((size_t)n * C_ + cin0) * 64 + h0 + hh) * 64 + w0 + wl] = lo2(acc[q][hh]);
            g_y[(((size_t)n * C_ + cin0 + 1) * 64 + h0 + hh) * 64 + w0 + wl] = hi2(acc[q][hh]);
        }
}

// ---------------------------------------------------------------------------
// K3: split-K partials of u[n,co,ci] = (1/64) sum_p t1[n,co,p]*y[n,ci,p]
// 32 chunks of 128 positions; 512 threads; f32x2 along co.
// ---------------------------------------------------------------------------
__global__ void k3_part(const float* __restrict__ x, const float* __restrict__ p1)
{
    __shared__ __align__(16) float as2[32 * 132];   // t1 chunk [kk][co]
    __shared__ __align__(16) float bs [32 * 132];   // y  chunk [kk][ci]
    const int kc = blockIdx.x, n = blockIdx.y;
    const int t = threadIdx.x;       // 512
    const int ty = t >> 5, tx = t & 31;
    const int lc = t >> 2, lk0 = (t & 3) * 8;

    u64 acc[4][4];
#pragma unroll
    for (int p = 0; p < 4; p++)
#pragma unroll
        for (int j = 0; j < 4; j++) acc[p][j] = 0ull;

    const int p0 = kc * 128;
    const float* xn = x + (size_t)n * C_ * HW;
    const float* yn = g_y + (size_t)n * C_ * HW;

    for (int kb = 0; kb < 4; kb++) {
        const int pb = p0 + kb * 32;
        const int h = pb >> 6;
        __syncthreads();
        float s = p1[lc * 64 + h] * (1.f / 64.f);
        float4 xa = *reinterpret_cast<const float4*>(&xn[(size_t)lc * HW + pb + lk0]);
        float4 xb = *reinterpret_cast<const float4*>(&xn[(size_t)lc * HW + pb + lk0 + 4]);
        float4 ya = *reinterpret_cast<const float4*>(&yn[(size_t)lc * HW + pb + lk0]);
        float4 yb = *reinterpret_cast<const float4*>(&yn[(size_t)lc * HW + pb + lk0 + 4]);
        as2[(lk0 + 0) * 132 + lc] = s * xa.x;
        as2[(lk0 + 1) * 132 + lc] = s * xa.y;
        as2[(lk0 + 2) * 132 + lc] = s * xa.z;
        as2[(lk0 + 3) * 132 + lc] = s * xa.w;
        as2[(lk0 + 4) * 132 + lc] = s * xb.x;
        as2[(lk0 + 5) * 132 + lc] = s * xb.y;
        as2[(lk0 + 6) * 132 + lc] = s * xb.z;
        as2[(lk0 + 7) * 132 + lc] = s * xb.w;
        bs[(lk0 + 0) * 132 + lc] = ya.x;
        bs[(lk0 + 1) * 132 + lc] = ya.y;
        bs[(lk0 + 2) * 132 + lc] = ya.z;
        bs[(lk0 + 3) * 132 + lc] = ya.w;
        bs[(lk0 + 4) * 132 + lc] = yb.x;
        bs[(lk0 + 5) * 132 + lc] = yb.y;
        bs[(lk0 + 6) * 132 + lc] = yb.z;
        bs[(lk0 + 7) * 132 + lc] = yb.w;
        __syncthreads();
#pragma unroll 4
        for (int kk = 0; kk < 32; kk++) {
            float4 b = *reinterpret_cast<const float4*>(&bs[kk * 132 + tx * 4]);
            u64 a0 = *reinterpret_cast<const u64*>(&as2[kk * 132 + ty * 8 + 0]);
            u64 a1 = *reinterpret_cast<const u64*>(&as2[kk * 132 + ty * 8 + 2]);
            u64 a2 = *reinterpret_cast<const u64*>(&as2[kk * 132 + ty * 8 + 4]);
            u64 a3 = *reinterpret_cast<const u64*>(&as2[kk * 132 + ty * 8 + 6]);
            u64 bb0 = pack2(b.x, b.x), bb1 = pack2(b.y, b.y);
            u64 bb2 = pack2(b.z, b.z), bb3 = pack2(b.w, b.w);
            fma2(acc[0][0], a0, bb0); fma2(acc[0][1], a0, bb1);
            fma2(acc[0][2], a0, bb2); fma2(acc[0][3], a0, bb3);
            fma2(acc[1][0], a1, bb0); fma2(acc[1][1], a1, bb1);
            fma2(acc[1][2], a1, bb2); fma2(acc[1][3], a1, bb3);
            fma2(acc[2][0], a2, bb0); fma2(acc[2][1], a2, bb1);
            fma2(acc[2][2], a2, bb2); fma2(acc[2][3], a2, bb3);
            fma2(acc[3][0], a3, bb0); fma2(acc[3][1], a3, bb1);
            fma2(acc[3][2], a3, bb2); fma2(acc[3][3], a3, bb3);
        }
    }

    float* up = g_up + ((size_t)(n * 32 + kc)) * C_ * C_;
#pragma unroll
    for (int p = 0; p < 4; p++) {
        int co0 = ty * 8 + 2 * p;
        float4 vl = make_float4(lo2(acc[p][0]), lo2(acc[p][1]),
                                lo2(acc[p][2]), lo2(acc[p][3]));
        float4 vh = make_float4(hi2(acc[p][0]), hi2(acc[p][1]),
                                hi2(acc[p][2]), hi2(acc[p][3]));
        *reinterpret_cast<float4*>(&up[co0 * 128 + tx * 4]) = vl;
        *reinterpret_cast<float4*>(&up[(co0 + 1) * 128 + tx * 4]) = vh;
    }
}

// K3b: reduce 32 split-K partials; write u transposed: g_u[n][ci][co]
__global__ void k3_red()
{
    int o = blockIdx.x * 256 + threadIdx.x;   // 131072
    int n = o >> 14, r = o & 16383;
    float s = 0.f;
#pragma unroll
    for (int kc = 0; kc < 32; kc++)
        s += g_up[(((size_t)(n * 32 + kc)) << 14) + r];
    int co = r >> 7, ci = r & 127;
    g_u[((size_t)n << 14) + ci * 128 + co] = s;
}

// ---------------------------------------------------------------------------
// K4: out = max( s3 * sum_ci u[n,co,ci]*t2[ci,p],  x[co,p] - 0.2*sum_jj t7 taps )
// same f32x2 structure as K1 (u already transposed in g_u).
// ---------------------------------------------------------------------------
__global__ void k4_out(const float* __restrict__ x, const float* __restrict__ p1,
                       float* __restrict__ out)
{
    __shared__ __align__(16) float xs [128 * 64];   // t2[ci][w]
    __shared__ __align__(16) float as2[16 * 128];   // u chunk [kk=ci][co]
    const int row = blockIdx.x, n = blockIdx.y;
    const int t = threadIdx.x;  // 128
    const int tx = t & 7, ty = t >> 3;
    const float* xn = x + (size_t)n * C_ * HW + row * 64;

    for (int r = 0; r < 64; r++) {
        int idx = r * 128 + t;
        int ci = idx >> 6, w = idx & 63;
        xs[idx] = (1.f + p1[ci * 64 + row]) * xn[(size_t)ci * HW + w];
    }

    u64 acc[4][8];
#pragma unroll
    for (int p = 0; p < 4; p++)
#pragma unroll
        for (int j = 0; j < 8; j++) acc[p][j] = 0ull;

    const float* un = g_u + ((size_t)n << 14);

    for (int kb = 0; kb < 8; kb++) {
        __syncthreads();
#pragma unroll
        for (int r = 0; r < 16; r++)
            as2[r * 128 + t] = un[kb * 2048 + r * 128 + t];
        __syncthreads();
#pragma unroll
        for (int kk = 0; kk < 16; kk++) {
            int k = kb * 16 + kk;
            float4 b0 = *reinterpret_cast<const float4*>(&xs[k * 64 + tx * 8]);
            float4 b1 = *reinterpret_cast<const float4*>(&xs[k * 64 + tx * 8 + 4]);
            u64 a0 = *reinterpret_cast<const u64*>(&as2[kk * 128 + ty * 8 + 0]);
            u64 a1 = *reinterpret_cast<const u64*>(&as2[kk * 128 + ty * 8 + 2]);
            u64 a2 = *reinterpret_cast<const u64*>(&as2[kk * 128 + ty * 8 + 4]);
            u64 a3 = *reinterpret_cast<const u64*>(&as2[kk * 128 + ty * 8 + 6]);
            u64 bb[8];
            bb[0] = pack2(b0.x, b0.x); bb[1] = pack2(b0.y, b0.y);
            bb[2] = pack2(b0.z, b0.z); bb[3] = pack2(b0.w, b0.w);
            bb[4] = pack2(b1.x, b1.x); bb[5] = pack2(b1.y, b1.y);
            bb[6] = pack2(b1.z, b1.z); bb[7] = pack2(b1.w, b1.w);
#pragma unroll
            for (int j = 0; j < 8; j++) {
                fma2(acc[0][j], a0, bb[j]);
                fma2(acc[1][j], a1, bb[j]);
                fma2(acc[2][j], a2, bb[j]);
                fma2(acc[3][j], a3, bb[j]);
            }
        }
    }

    const float s3 = 0.01928793f;    // 1/sqrt(2688)
#pragma unroll
    for (int p = 0; p < 4; p++) {
#pragma unroll
        for (int half = 0; half < 2; half++) {
            int co = ty * 8 + 2 * p + half;
            const float* t7r = g_t7 + ((size_t)n * C_ + co) * HW + row * 64;
            const float* xr = xn + (size_t)co * HW;
            float* orow = out + ((size_t)n * C_ + co) * HW + row * 64;
#pragma unroll
            for (int j = 0; j < 8; j++) {
                int pp = tx * 8 + j;
                float a = half ? hi2(acc[p][j]) : lo2(acc[p][j]);
                float sum = 0.f;
#pragma unroll
                for (int jj = 0; jj < 5; jj++) {
                    int wp = pp + 3 * jj - 6;
                    if ((unsigned)wp < 64u) sum += __ldg(&t7r[wp]);
                }
                float t12 = xr[pp] - 0.2f * sum;
                orow[pp] = fmaxf(s3 * a, t12);
            }
        }
    }
}

// ---------------------------------------------------------------------------
extern "C" void kernel_launch(void* const* d_in, const int* in_sizes, int n_in,
                              void* d_out, int out_size)
{
    const float* x   = (const float*)d_in[0];   // (8,128,64,64)
    const float* p1w = (const float*)d_in[1];   // (1,128,64,1)
    const float* p7w = (const float*)d_in[2];   // (128,128)
    const float* p10 = (const float*)d_in[3];   // (2688,32)
    float* out = (float*)d_out;

    k0_tr  <<<64, 256>>>(p7w);
    k1_t7  <<<dim3(64, 8), 128>>>(x);
    k2_conv<<<dim3(16, 4, 8), 128>>>(x, p10);
    k3_part<<<dim3(32, 8), 512>>>(x, p1w);
    k3_red <<<512, 256>>>();
    k4_out <<<dim3(64, 8), 128>>>(x, p1w, out);
}

// round 6
// speedup vs baseline: 1.0782x; 1.0782x over previous
#include <cuda_runtime.h>

#define N_ 8
#define C_ 128
#define H_ 64
#define W_ 64
#define HW 4096

typedef unsigned long long u64;

// scratch (no allocs allowed)
__device__ float g_t7 [N_ * C_ * HW];            // 16 MB
__device__ float g_y  [N_ * C_ * HW];            // 16 MB
__device__ float g_up [N_ * 32 * C_ * C_];       // 16 MB split-K partials
__device__ float g_u  [N_ * C_ * C_];            // 512 KB (transposed: [n][ci][co])
__device__ float g_p7t[C_ * C_];                 // p7 transposed [k][co]

// ---- f32x2 helpers -------------------------------------------------------
__device__ __forceinline__ u64 pack2(float a, float b) {
    u64 r;
    asm("mov.b64 %0, {%1, %2};" : "=l"(r) : "f"(a), "f"(b));
    return r;
}
__device__ __forceinline__ void fma2(u64& d, u64 a, u64 b) {
    asm("fma.rn.f32x2 %0, %1, %2, %0;" : "+l"(d) : "l"(a), "l"(b));
}
__device__ __forceinline__ float lo2(u64 v) { return __uint_as_float((unsigned)v); }
__device__ __forceinline__ float hi2(u64 v) { return __uint_as_float((unsigned)(v >> 32)); }

// ---------------------------------------------------------------------------
// K0: transpose p7 -> g_p7t[k][co]
// ---------------------------------------------------------------------------
__global__ void k0_tr(const float* __restrict__ p7)
{
    int idx = blockIdx.x * 256 + threadIdx.x;   // 16384
    int kk = idx >> 7, co = idx & 127;
    g_p7t[idx] = p7[co * 128 + kk];
}

// ---------------------------------------------------------------------------
// K1: t7[n,co,row,:] = sum_c p7[co,c] * relu(x[n,c,row,:])
// 128 threads: ty(16) x 8 co (4 f32x2 pairs), tx(8) x 8 w
// ---------------------------------------------------------------------------
__global__ void k1_t7(const float* __restrict__ x)
{
    __shared__ __align__(16) float xs [128 * 64];   // relu(x)[ci][w]
    __shared__ __align__(16) float as2[16 * 128];   // p7t chunk [kk][co]
    const int row = blockIdx.x, n = blockIdx.y;
    const int t = threadIdx.x;
    const int tx = t & 7, ty = t >> 3;
    const float* xn = x + (size_t)n * C_ * HW + row * 64;

#pragma unroll
    for (int r = 0; r < 16; r++) {
        int idx4 = r * 512 + t * 4;
        int ci = idx4 >> 6, w = idx4 & 63;
        float4 v = *reinterpret_cast<const float4*>(&xn[(size_t)ci * HW + w]);
        v.x = fmaxf(v.x, 0.f); v.y = fmaxf(v.y, 0.f);
        v.z = fmaxf(v.z, 0.f); v.w = fmaxf(v.w, 0.f);
        *reinterpret_cast<float4*>(&xs[idx4]) = v;
    }

    u64 acc[4][8];
#pragma unroll
    for (int p = 0; p < 4; p++)
#pragma unroll
        for (int j = 0; j < 8; j++) acc[p][j] = 0ull;

    for (int kb = 0; kb < 8; kb++) {
        __syncthreads();
#pragma unroll
        for (int r = 0; r < 4; r++)
            *reinterpret_cast<float4*>(&as2[r * 512 + t * 4]) =
                *reinterpret_cast<const float4*>(&g_p7t[kb * 2048 + r * 512 + t * 4]);
        __syncthreads();
#pragma unroll
        for (int kk = 0; kk < 16; kk++) {
            int k = kb * 16 + kk;
            float4 b0 = *reinterpret_cast<const float4*>(&xs[k * 64 + tx * 8]);
            float4 b1 = *reinterpret_cast<const float4*>(&xs[k * 64 + tx * 8 + 4]);
            u64 a0 = *reinterpret_cast<const u64*>(&as2[kk * 128 + ty * 8 + 0]);
            u64 a1 = *reinterpret_cast<const u64*>(&as2[kk * 128 + ty * 8 + 2]);
            u64 a2 = *reinterpret_cast<const u64*>(&as2[kk * 128 + ty * 8 + 4]);
            u64 a3 = *reinterpret_cast<const u64*>(&as2[kk * 128 + ty * 8 + 6]);
            u64 bb[8];
            bb[0] = pack2(b0.x, b0.x); bb[1] = pack2(b0.y, b0.y);
            bb[2] = pack2(b0.z, b0.z); bb[3] = pack2(b0.w, b0.w);
            bb[4] = pack2(b1.x, b1.x); bb[5] = pack2(b1.y, b1.y);
            bb[6] = pack2(b1.z, b1.z); bb[7] = pack2(b1.w, b1.w);
#pragma unroll
            for (int j = 0; j < 8; j++) {
                fma2(acc[0][j], a0, bb[j]);
                fma2(acc[1][j], a1, bb[j]);
                fma2(acc[2][j], a2, bb[j]);
                fma2(acc[3][j], a3, bb[j]);
            }
        }
    }

    float* t7n = g_t7 + (size_t)n * C_ * HW + row * 64;
#pragma unroll
    for (int p = 0; p < 4; p++) {
        int co0 = ty * 8 + 2 * p;
#pragma unroll
        for (int jq = 0; jq < 2; jq++) {
            float4 vl = make_float4(lo2(acc[p][jq*4+0]), lo2(acc[p][jq*4+1]),
                                    lo2(acc[p][jq*4+2]), lo2(acc[p][jq*4+3]));
            float4 vh = make_float4(hi2(acc[p][jq*4+0]), hi2(acc[p][jq*4+1]),
                                    hi2(acc[p][jq*4+2]), hi2(acc[p][jq*4+3]));
            *reinterpret_cast<float4*>(&t7n[(size_t)co0 * HW + tx * 8 + jq * 4]) = vl;
            *reinterpret_cast<float4*>(&t7n[(size_t)(co0 + 1) * HW + tx * 8 + jq * 4]) = vh;
        }
    }
}

// ---------------------------------------------------------------------------
// K2: grouped 3x7 conv, f32x2 along cin.
// 128 threads = 32 w-lanes x 4 cin-octs; thread: 8 cin (4 pairs) x 8 h.
// ---------------------------------------------------------------------------
__global__ void k2_conv(const float* __restrict__ x, const float* __restrict__ p10)
{
    __shared__ __align__(16) float xs[8 * 10 * 38];   // [ci][hh][ww]  3040
    __shared__ __align__(16) float ws[8 * 21 * 32];   // [ci][k][cin]  5376
    const int tile = blockIdx.x;        // 0..15
    const int g = blockIdx.y, n = blockIdx.z;
    const int h0 = (tile >> 1) * 8, w0 = (tile & 1) * 32;
    const int t = threadIdx.x;          // 128
    const int wl = t & 31, oct = t >> 5;

    u64 acc[4][8];
#pragma unroll
    for (int q = 0; q < 4; q++)
#pragma unroll
        for (int hh = 0; hh < 8; hh++) acc[q][hh] = 0ull;

    for (int cc = 0; cc < 4; cc++) {
        __syncthreads();
        for (int idx = t; idx < 3040; idx += 128) {
            int ci = idx / 380;
            int rem = idx - ci * 380;
            int hh = rem / 38, ww = rem - hh * 38;
            int hg = h0 - 1 + hh, wg = w0 - 3 + ww;
            float v = 0.f;
            if ((unsigned)hg < 64u && (unsigned)wg < 64u)
                v = x[(((size_t)n * C_ + g * 32 + cc * 8 + ci) * 64 + hg) * 64 + wg];
            xs[idx] = v;
        }
        // ws[idx] = p10[(g*32+cc*8)*672 + idx]  (contiguous copy)
        {
            const float* wsrc = p10 + (size_t)(g * 32 + cc * 8) * 672;
            for (int idx4 = t * 4; idx4 < 5376; idx4 += 512)
                *reinterpret_cast<float4*>(&ws[idx4]) =
                    *reinterpret_cast<const float4*>(&wsrc[idx4]);
        }
        __syncthreads();

#pragma unroll 1
        for (int ci = 0; ci < 8; ci++) {
#pragma unroll
            for (int k = 0; k < 21; k++) {
                const int di = k / 7, dj = k - di * 7;
                const float* wp = &ws[(ci * 21 + k) * 32 + oct * 8];
                u64 w0p = *reinterpret_cast<const u64*>(wp + 0);
                u64 w1p = *reinterpret_cast<const u64*>(wp + 2);
                u64 w2p = *reinterpret_cast<const u64*>(wp + 4);
                u64 w3p = *reinterpret_cast<const u64*>(wp + 6);
                const float* xr = &xs[(ci * 10 + di) * 38 + wl + dj];
#pragma unroll
                for (int hh = 0; hh < 8; hh++) {
                    float xv = xr[hh * 38];
                    u64 xx = pack2(xv, xv);
                    fma2(acc[0][hh], w0p, xx);
                    fma2(acc[1][hh], w1p, xx);
                    fma2(acc[2][hh], w2p, xx);
                    fma2(acc[3][hh], w3p, xx);
                }
            }
        }
    }

#pragma unroll
    for (int q = 0; q < 4; q++)
#pragma unroll
        for (int hh = 0; hh < 8; hh++) {
            int cin0 = g * 32 + oct * 8 + 2 * q;
            g_y[(((size_t)n * C_ + cin0) * 64 + h0 + hh) * 64 + w0 + wl] = lo2(acc[q][hh]);
            g_y[(((size_t)n * C_ + cin0 + 1) * 64 + h0 + hh) * 64 + w0 + wl] = hi2(acc[q][hh]);
        }
}

// ---------------------------------------------------------------------------
// K3: split-K partials of u[n,co,ci] = (1/64) sum_p t1[n,co,p]*y[n,ci,p]
// 32 chunks of 128 positions; 512 threads; f32x2 along co.
// ---------------------------------------------------------------------------
__global__ void k3_part(const float* __restrict__ x, const float* __restrict__ p1)
{
    __shared__ __align__(16) float as2[32 * 132];   // t1 chunk [kk][co]
    __shared__ __align__(16) float bs [32 * 132];   // y  chunk [kk][ci]
    const int kc = blockIdx.x, n = blockIdx.y;
    const int t = threadIdx.x;       // 512
    const int ty = t >> 5, tx = t & 31;
    const int lc = t >> 2, lk0 = (t & 3) * 8;

    u64 acc[4][4];
#pragma unroll
    for (int p = 0; p < 4; p++)
#pragma unroll
        for (int j = 0; j < 4; j++) acc[p][j] = 0ull;

    const int p0 = kc * 128;
    const float* xn = x + (size_t)n * C_ * HW;
    const float* yn = g_y + (size_t)n * C_ * HW;

    for (int kb = 0; kb < 4; kb++) {
        const int pb = p0 + kb * 32;
        const int h = pb >> 6;
        __syncthreads();
        float s = p1[lc * 64 + h] * (1.f / 64.f);
        float4 xa = *reinterpret_cast<const float4*>(&xn[(size_t)lc * HW + pb + lk0]);
        float4 xb = *reinterpret_cast<const float4*>(&xn[(size_t)lc * HW + pb + lk0 + 4]);
        float4 ya = *reinterpret_cast<const float4*>(&yn[(size_t)lc * HW + pb + lk0]);
        float4 yb = *reinterpret_cast<const float4*>(&yn[(size_t)lc * HW + pb + lk0 + 4]);
        as2[(lk0 + 0) * 132 + lc] = s * xa.x;
        as2[(lk0 + 1) * 132 + lc] = s * xa.y;
        as2[(lk0 + 2) * 132 + lc] = s * xa.z;
        as2[(lk0 + 3) * 132 + lc] = s * xa.w;
        as2[(lk0 + 4) * 132 + lc] = s * xb.x;
        as2[(lk0 + 5) * 132 + lc] = s * xb.y;
        as2[(lk0 + 6) * 132 + lc] = s * xb.z;
        as2[(lk0 + 7) * 132 + lc] = s * xb.w;
        bs[(lk0 + 0) * 132 + lc] = ya.x;
        bs[(lk0 + 1) * 132 + lc] = ya.y;
        bs[(lk0 + 2) * 132 + lc] = ya.z;
        bs[(lk0 + 3) * 132 + lc] = ya.w;
        bs[(lk0 + 4) * 132 + lc] = yb.x;
        bs[(lk0 + 5) * 132 + lc] = yb.y;
        bs[(lk0 + 6) * 132 + lc] = yb.z;
        bs[(lk0 + 7) * 132 + lc] = yb.w;
        __syncthreads();
#pragma unroll 4
        for (int kk = 0; kk < 32; kk++) {
            float4 b = *reinterpret_cast<const float4*>(&bs[kk * 132 + tx * 4]);
            u64 a0 = *reinterpret_cast<const u64*>(&as2[kk * 132 + ty * 8 + 0]);
            u64 a1 = *reinterpret_cast<const u64*>(&as2[kk * 132 + ty * 8 + 2]);
            u64 a2 = *reinterpret_cast<const u64*>(&as2[kk * 132 + ty * 8 + 4]);
            u64 a3 = *reinterpret_cast<const u64*>(&as2[kk * 132 + ty * 8 + 6]);
            u64 bb0 = pack2(b.x, b.x), bb1 = pack2(b.y, b.y);
            u64 bb2 = pack2(b.z, b.z), bb3 = pack2(b.w, b.w);
            fma2(acc[0][0], a0, bb0); fma2(acc[0][1], a0, bb1);
            fma2(acc[0][2], a0, bb2); fma2(acc[0][3], a0, bb3);
            fma2(acc[1][0], a1, bb0); fma2(acc[1][1], a1, bb1);
            fma2(acc[1][2], a1, bb2); fma2(acc[1][3], a1, bb3);
            fma2(acc[2][0], a2, bb0); fma2(acc[2][1], a2, bb1);
            fma2(acc[2][2], a2, bb2); fma2(acc[2][3], a2, bb3);
            fma2(acc[3][0], a3, bb0); fma2(acc[3][1], a3, bb1);
            fma2(acc[3][2], a3, bb2); fma2(acc[3][3], a3, bb3);
        }
    }

    float* up = g_up + ((size_t)(n * 32 + kc)) * C_ * C_;
#pragma unroll
    for (int p = 0; p < 4; p++) {
        int co0 = ty * 8 + 2 * p;
        float4 vl = make_float4(lo2(acc[p][0]), lo2(acc[p][1]),
                                lo2(acc[p][2]), lo2(acc[p][3]));
        float4 vh = make_float4(hi2(acc[p][0]), hi2(acc[p][1]),
                                hi2(acc[p][2]), hi2(acc[p][3]));
        *reinterpret_cast<float4*>(&up[co0 * 128 + tx * 4]) = vl;
        *reinterpret_cast<float4*>(&up[(co0 + 1) * 128 + tx * 4]) = vh;
    }
}

// K3b: reduce 32 split-K partials; write u transposed: g_u[n][ci][co]
__global__ void k3_red()
{
    int o = blockIdx.x * 256 + threadIdx.x;   // 131072
    int n = o >> 14, r = o & 16383;
    float s = 0.f;
#pragma unroll
    for (int kc = 0; kc < 32; kc++)
        s += g_up[(((size_t)(n * 32 + kc)) << 14) + r];
    int co = r >> 7, ci = r & 127;
    g_u[((size_t)n << 14) + ci * 128 + co] = s;
}

// ---------------------------------------------------------------------------
// K4: out = max( s3 * sum_ci u[n,co,ci]*t2[ci,p],  x[co,p] - 0.2*sum_jj t7 taps )
// f32x2 GEMM like K1; epilogue reuses xs smem for the t7 row-slab.
// ---------------------------------------------------------------------------
__global__ void k4_out(const float* __restrict__ x, const float* __restrict__ p1,
                       float* __restrict__ out)
{
    __shared__ __align__(16) float xs [128 * 64];   // t2[ci][w], later t7[co][w]
    __shared__ __align__(16) float as2[16 * 128];   // u chunk [kk=ci][co]
    const int row = blockIdx.x, n = blockIdx.y;
    const int t = threadIdx.x;  // 128
    const int tx = t & 7, ty = t >> 3;
    const float* xn = x + (size_t)n * C_ * HW + row * 64;

#pragma unroll
    for (int r = 0; r < 16; r++) {
        int idx4 = r * 512 + t * 4;
        int ci = idx4 >> 6, w = idx4 & 63;
        float s = 1.f + p1[ci * 64 + row];
        float4 v = *reinterpret_cast<const float4*>(&xn[(size_t)ci * HW + w]);
        v.x *= s; v.y *= s; v.z *= s; v.w *= s;
        *reinterpret_cast<float4*>(&xs[idx4]) = v;
    }

    u64 acc[4][8];
#pragma unroll
    for (int p = 0; p < 4; p++)
#pragma unroll
        for (int j = 0; j < 8; j++) acc[p][j] = 0ull;

    const float* un = g_u + ((size_t)n << 14);

    for (int kb = 0; kb < 8; kb++) {
        __syncthreads();
#pragma unroll
        for (int r = 0; r < 4; r++)
            *reinterpret_cast<float4*>(&as2[r * 512 + t * 4]) =
                *reinterpret_cast<const float4*>(&un[kb * 2048 + r * 512 + t * 4]);
        __syncthreads();
#pragma unroll
        for (int kk = 0; kk < 16; kk++) {
            int k = kb * 16 + kk;
            float4 b0 = *reinterpret_cast<const float4*>(&xs[k * 64 + tx * 8]);
            float4 b1 = *reinterpret_cast<const float4*>(&xs[k * 64 + tx * 8 + 4]);
            u64 a0 = *reinterpret_cast<const u64*>(&as2[kk * 128 + ty * 8 + 0]);
            u64 a1 = *reinterpret_cast<const u64*>(&as2[kk * 128 + ty * 8 + 2]);
            u64 a2 = *reinterpret_cast<const u64*>(&as2[kk * 128 + ty * 8 + 4]);
            u64 a3 = *reinterpret_cast<const u64*>(&as2[kk * 128 + ty * 8 + 6]);
            u64 bb[8];
            bb[0] = pack2(b0.x, b0.x); bb[1] = pack2(b0.y, b0.y);
            bb[2] = pack2(b0.z, b0.z); bb[3] = pack2(b0.w, b0.w);
            bb[4] = pack2(b1.x, b1.x); bb[5] = pack2(b1.y, b1.y);
            bb[6] = pack2(b1.z, b1.z); bb[7] = pack2(b1.w, b1.w);
#pragma unroll
            for (int j = 0; j < 8; j++) {
                fma2(acc[0][j], a0, bb[j]);
                fma2(acc[1][j], a1, bb[j]);
                fma2(acc[2][j], a2, bb[j]);
                fma2(acc[3][j], a3, bb[j]);
            }
        }
    }

    // epilogue: reuse xs for t7[n,:,row,:]
    __syncthreads();
#pragma unroll
    for (int r = 0; r < 16; r++) {
        int idx4 = r * 512 + t * 4;
        int ci = idx4 >> 6, w = idx4 & 63;
        *reinterpret_cast<float4*>(&xs[idx4]) =
            *reinterpret_cast<const float4*>(
                &g_t7[((size_t)n * C_ + ci) * HW + row * 64 + w]);
    }
    __syncthreads();

    const float s3 = 0.01928793f;    // 1/sqrt(2688)
#pragma unroll
    for (int p = 0; p < 4; p++) {
#pragma unroll
        for (int half = 0; half < 2; half++) {
            int co = ty * 8 + 2 * p + half;
            const float* xr = xn + (size_t)co * HW;
            float4 xv0 = *reinterpret_cast<const float4*>(&xr[tx * 8]);
            float4 xv1 = *reinterpret_cast<const float4*>(&xr[tx * 8 + 4]);
            float xv[8] = {xv0.x, xv0.y, xv0.z, xv0.w, xv1.x, xv1.y, xv1.z, xv1.w};
            float res[8];
#pragma unroll
            for (int j = 0; j < 8; j++) {
                int pp = tx * 8 + j;
                float a = half ? hi2(acc[p][j]) : lo2(acc[p][j]);
                float sum = 0.f;
#pragma unroll
                for (int jj = 0; jj < 5; jj++) {
                    int wp = pp + 3 * jj - 6;
                    if ((unsigned)wp < 64u) sum += xs[co * 64 + wp];
                }
                float t12 = xv[j] - 0.2f * sum;
                res[j] = fmaxf(s3 * a, t12);
            }
            float* orow = out + ((size_t)n * C_ + co) * HW + row * 64;
            *reinterpret_cast<float4*>(&orow[tx * 8]) =
                make_float4(res[0], res[1], res[2], res[3]);
            *reinterpret_cast<float4*>(&orow[tx * 8 + 4]) =
                make_float4(res[4], res[5], res[6], res[7]);
        }
    }
}

// ---------------------------------------------------------------------------
extern "C" void kernel_launch(void* const* d_in, const int* in_sizes, int n_in,
                              void* d_out, int out_size)
{
    const float* x   = (const float*)d_in[0];   // (8,128,64,64)
    const float* p1w = (const float*)d_in[1];   // (1,128,64,1)
    const float* p7w = (const float*)d_in[2];   // (128,128)
    const float* p10 = (const float*)d_in[3];   // (2688,32)
    float* out = (float*)d_out;

    k0_tr  <<<64, 256>>>(p7w);
    k1_t7  <<<dim3(64, 8), 128>>>(x);
    k2_conv<<<dim3(16, 4, 8), 128>>>(x, p10);
    k3_part<<<dim3(32, 8), 512>>>(x, p1w);
    k3_red <<<512, 256>>>();
    k4_out <<<dim3(64, 8), 128>>>(x, p1w, out);
}

// round 7
// speedup vs baseline: 1.1542x; 1.0704x over previous
#include <cuda_runtime.h>
#include <cstdint>

#define N_ 8
#define C_ 128
#define H_ 64
#define W_ 64
#define HW 4096

typedef unsigned long long u64;

// scratch (no allocs allowed)
__device__ float g_t7 [N_ * C_ * HW];            // 16 MB
__device__ float g_y  [N_ * C_ * HW];            // 16 MB
__device__ float g_up [N_ * 32 * C_ * C_];       // 16 MB split-K partials
__device__ float g_u  [N_ * C_ * C_];            // 512 KB (transposed: [n][ci][co])
__device__ float g_p7t[C_ * C_];                 // p7 transposed [k][co]

// ---- helpers ---------------------------------------------------------------
__device__ __forceinline__ u64 pack2(float a, float b) {
    u64 r;
    asm("mov.b64 %0, {%1, %2};" : "=l"(r) : "f"(a), "f"(b));
    return r;
}
__device__ __forceinline__ void fma2(u64& d, u64 a, u64 b) {
    asm("fma.rn.f32x2 %0, %1, %2, %0;" : "+l"(d) : "l"(a), "l"(b));
}
__device__ __forceinline__ float lo2(u64 v) { return __uint_as_float((unsigned)v); }
__device__ __forceinline__ float hi2(u64 v) { return __uint_as_float((unsigned)(v >> 32)); }

__device__ __forceinline__ uint32_t s2u(const void* p) {
    return (uint32_t)__cvta_generic_to_shared(p);
}
__device__ __forceinline__ void cpa16(uint32_t dst, const void* src) {
    asm volatile("cp.async.cg.shared.global [%0], [%1], 16;" :: "r"(dst), "l"(src));
}
__device__ __forceinline__ void cpa4z(uint32_t dst, const void* src, bool p) {
    int sz = p ? 4 : 0;
    asm volatile("cp.async.ca.shared.global [%0], [%1], 4, %2;"
                 :: "r"(dst), "l"(src), "r"(sz));
}
__device__ __forceinline__ void cpa_commit() {
    asm volatile("cp.async.commit_group;" ::: "memory");
}
__device__ __forceinline__ void cpa_wait0() {
    asm volatile("cp.async.wait_group 0;" ::: "memory");
}

// ---------------------------------------------------------------------------
// K0: transpose p7 -> g_p7t[k][co]
// ---------------------------------------------------------------------------
__global__ void k0_tr(const float* __restrict__ p7)
{
    int idx = blockIdx.x * 256 + threadIdx.x;   // 16384
    int kk = idx >> 7, co = idx & 127;
    g_p7t[idx] = p7[co * 128 + kk];
}

// ---------------------------------------------------------------------------
// K1: t7[n,co,row,:] = sum_c p7[co,c] * relu(x[n,c,row,:])
// 128 threads: ty(16) x 8 co (4 f32x2 pairs), tx(8) x 8 w
// double-buffered weight chunks via cp.async
// ---------------------------------------------------------------------------
__global__ void k1_t7(const float* __restrict__ x)
{
    __shared__ __align__(16) float xs [128 * 64];     // relu(x)[ci][w] 32KB
    __shared__ __align__(16) float as2[2][2048];      // p7t chunks [kk][co] 16KB
    const int row = blockIdx.x, n = blockIdx.y;
    const int t = threadIdx.x;
    const int tx = t & 7, ty = t >> 3;
    const float* xn = x + (size_t)n * C_ * HW + row * 64;

    // kick off weight chunk 0
#pragma unroll
    for (int r = 0; r < 4; r++)
        cpa16(s2u(&as2[0][r * 512 + t * 4]), &g_p7t[r * 512 + t * 4]);
    cpa_commit();

#pragma unroll
    for (int r = 0; r < 16; r++) {
        int idx4 = r * 512 + t * 4;
        int ci = idx4 >> 6, w = idx4 & 63;
        float4 v = *reinterpret_cast<const float4*>(&xn[(size_t)ci * HW + w]);
        v.x = fmaxf(v.x, 0.f); v.y = fmaxf(v.y, 0.f);
        v.z = fmaxf(v.z, 0.f); v.w = fmaxf(v.w, 0.f);
        *reinterpret_cast<float4*>(&xs[idx4]) = v;
    }

    u64 acc[4][8];
#pragma unroll
    for (int p = 0; p < 4; p++)
#pragma unroll
        for (int j = 0; j < 8; j++) acc[p][j] = 0ull;

    cpa_wait0();
    __syncthreads();

    for (int kb = 0; kb < 8; kb++) {
        const int cur = kb & 1;
        if (kb < 7) {
#pragma unroll
            for (int r = 0; r < 4; r++)
                cpa16(s2u(&as2[cur ^ 1][r * 512 + t * 4]),
                      &g_p7t[(kb + 1) * 2048 + r * 512 + t * 4]);
            cpa_commit();
        }
#pragma unroll
        for (int kk = 0; kk < 16; kk++) {
            int k = kb * 16 + kk;
            float4 b0 = *reinterpret_cast<const float4*>(&xs[k * 64 + tx * 8]);
            float4 b1 = *reinterpret_cast<const float4*>(&xs[k * 64 + tx * 8 + 4]);
            u64 a0 = *reinterpret_cast<const u64*>(&as2[cur][kk * 128 + ty * 8 + 0]);
            u64 a1 = *reinterpret_cast<const u64*>(&as2[cur][kk * 128 + ty * 8 + 2]);
            u64 a2 = *reinterpret_cast<const u64*>(&as2[cur][kk * 128 + ty * 8 + 4]);
            u64 a3 = *reinterpret_cast<const u64*>(&as2[cur][kk * 128 + ty * 8 + 6]);
            u64 bb[8];
            bb[0] = pack2(b0.x, b0.x); bb[1] = pack2(b0.y, b0.y);
            bb[2] = pack2(b0.z, b0.z); bb[3] = pack2(b0.w, b0.w);
            bb[4] = pack2(b1.x, b1.x); bb[5] = pack2(b1.y, b1.y);
            bb[6] = pack2(b1.z, b1.z); bb[7] = pack2(b1.w, b1.w);
#pragma unroll
            for (int j = 0; j < 8; j++) {
                fma2(acc[0][j], a0, bb[j]);
                fma2(acc[1][j], a1, bb[j]);
                fma2(acc[2][j], a2, bb[j]);
                fma2(acc[3][j], a3, bb[j]);
            }
        }
        if (kb < 7) { cpa_wait0(); __syncthreads(); }
    }

    float* t7n = g_t7 + (size_t)n * C_ * HW + row * 64;
#pragma unroll
    for (int p = 0; p < 4; p++) {
        int co0 = ty * 8 + 2 * p;
#pragma unroll
        for (int jq = 0; jq < 2; jq++) {
            float4 vl = make_float4(lo2(acc[p][jq*4+0]), lo2(acc[p][jq*4+1]),
                                    lo2(acc[p][jq*4+2]), lo2(acc[p][jq*4+3]));
            float4 vh = make_float4(hi2(acc[p][jq*4+0]), hi2(acc[p][jq*4+1]),
                                    hi2(acc[p][jq*4+2]), hi2(acc[p][jq*4+3]));
            *reinterpret_cast<float4*>(&t7n[(size_t)co0 * HW + tx * 8 + jq * 4]) = vl;
            *reinterpret_cast<float4*>(&t7n[(size_t)(co0 + 1) * HW + tx * 8 + jq * 4]) = vh;
        }
    }
}

// ---------------------------------------------------------------------------
// K2: grouped 3x7 conv, f32x2 along cin; ci-chunks of 4, double-buffered via
// cp.async (x halo gets zero-fill).
// 128 threads = 32 w-lanes x 4 cin-octs; thread: 8 cin (4 pairs) x 8 h.
// ---------------------------------------------------------------------------
__global__ void __launch_bounds__(128) k2_conv(const float* __restrict__ x,
                                               const float* __restrict__ p10)
{
    __shared__ __align__(16) float xs[2][1520];   // [ci4][hh10][ww38]
    __shared__ __align__(16) float ws[2][2688];   // [ci4][k21][cin32]
    const int tile = blockIdx.x;        // 0..15
    const int g = blockIdx.y, n = blockIdx.z;
    const int h0 = (tile >> 1) * 8, w0 = (tile & 1) * 32;
    const int t = threadIdx.x;          // 128
    const int wl = t & 31, oct = t >> 5;

    auto load_chunk = [&](int cc, int b) {
        for (int idx = t; idx < 1520; idx += 128) {
            int ci = idx / 380;
            int rem = idx - ci * 380;
            int hh = rem / 38, ww = rem - hh * 38;
            int hg = h0 - 1 + hh, wg = w0 - 3 + ww;
            bool p = ((unsigned)hg < 64u) && ((unsigned)wg < 64u);
            const float* src = p
                ? &x[(((size_t)n * C_ + g * 32 + cc * 4 + ci) * 64 + hg) * 64 + wg]
                : x;
            cpa4z(s2u(&xs[b][idx]), src, p);
        }
        const float* wsrc = p10 + (size_t)(g * 32 + cc * 4) * 672;
        for (int i4 = t * 4; i4 < 2688; i4 += 512)
            cpa16(s2u(&ws[b][i4]), wsrc + i4);
        cpa_commit();
    };

    u64 acc[4][8];
#pragma unroll
    for (int q = 0; q < 4; q++)
#pragma unroll
        for (int hh = 0; hh < 8; hh++) acc[q][hh] = 0ull;

    load_chunk(0, 0);
    cpa_wait0();
    __syncthreads();

    for (int cc = 0; cc < 8; cc++) {
        const int cur = cc & 1;
        if (cc < 7) load_chunk(cc + 1, cur ^ 1);

#pragma unroll 1
        for (int ci = 0; ci < 4; ci++) {
#pragma unroll
            for (int k = 0; k < 21; k++) {
                const int di = k / 7, dj = k - di * 7;
                const float* wp = &ws[cur][(ci * 21 + k) * 32 + oct * 8];
                u64 w0p = *reinterpret_cast<const u64*>(wp + 0);
                u64 w1p = *reinterpret_cast<const u64*>(wp + 2);
                u64 w2p = *reinterpret_cast<const u64*>(wp + 4);
                u64 w3p = *reinterpret_cast<const u64*>(wp + 6);
                const float* xr = &xs[cur][(ci * 10 + di) * 38 + wl + dj];
#pragma unroll
                for (int hh = 0; hh < 8; hh++) {
                    float xv = xr[hh * 38];
                    u64 xx = pack2(xv, xv);
                    fma2(acc[0][hh], w0p, xx);
                    fma2(acc[1][hh], w1p, xx);
                    fma2(acc[2][hh], w2p, xx);
                    fma2(acc[3][hh], w3p, xx);
                }
            }
        }
        if (cc < 7) { cpa_wait0(); __syncthreads(); }
    }

#pragma unroll
    for (int q = 0; q < 4; q++)
#pragma unroll
        for (int hh = 0; hh < 8; hh++) {
            int cin0 = g * 32 + oct * 8 + 2 * q;
            g_y[(((size_t)n * C_ + cin0) * 64 + h0 + hh) * 64 + w0 + wl] = lo2(acc[q][hh]);
            g_y[(((size_t)n * C_ + cin0 + 1) * 64 + h0 + hh) * 64 + w0 + wl] = hi2(acc[q][hh]);
        }
}

// ---------------------------------------------------------------------------
// K3: split-K partials of u[n,co,ci] = (1/64) sum_p t1[n,co,p]*y[n,ci,p]
// 32 chunks of 128 p; 8 sub-chunks of 16 p, double-buffered with reg staging.
// 512 threads; f32x2 along co.
// ---------------------------------------------------------------------------
__global__ void __launch_bounds__(512, 2) k3_part(const float* __restrict__ x,
                                                  const float* __restrict__ p1)
{
    __shared__ __align__(16) float as2[2][16 * 132];  // t1 [kk][co]
    __shared__ __align__(16) float bs [2][16 * 132];  // y  [kk][ci]
    const int kc = blockIdx.x, n = blockIdx.y;
    const int t = threadIdx.x;       // 512
    const int ty = t >> 5, tx = t & 31;
    const int lc = t >> 2, lk0 = (t & 3) * 4;

    const int p0 = kc * 128;
    const float* xp = x   + (size_t)n * C_ * HW + (size_t)lc * HW + p0 + lk0;
    const float* yp = g_y + (size_t)n * C_ * HW + (size_t)lc * HW + p0 + lk0;

    float4 xa, ya; float s;
    auto ldg = [&](int kb) {
        xa = *reinterpret_cast<const float4*>(xp + kb * 16);
        ya = *reinterpret_cast<const float4*>(yp + kb * 16);
        int h = (p0 + kb * 16) >> 6;
        s = p1[lc * 64 + h] * (1.f / 64.f);
    };
    auto sts = [&](int b) {
        as2[b][(lk0 + 0) * 132 + lc] = s * xa.x;
        as2[b][(lk0 + 1) * 132 + lc] = s * xa.y;
        as2[b][(lk0 + 2) * 132 + lc] = s * xa.z;
        as2[b][(lk0 + 3) * 132 + lc] = s * xa.w;
        bs [b][(lk0 + 0) * 132 + lc] = ya.x;
        bs [b][(lk0 + 1) * 132 + lc] = ya.y;
        bs [b][(lk0 + 2) * 132 + lc] = ya.z;
        bs [b][(lk0 + 3) * 132 + lc] = ya.w;
    };

    u64 acc[4][4];
#pragma unroll
    for (int p = 0; p < 4; p++)
#pragma unroll
        for (int j = 0; j < 4; j++) acc[p][j] = 0ull;

    ldg(0); sts(0);
    __syncthreads();

    for (int kb = 0; kb < 8; kb++) {
        const int cur = kb & 1;
        if (kb < 7) ldg(kb + 1);
#pragma unroll
        for (int kk = 0; kk < 16; kk++) {
            float4 b = *reinterpret_cast<const float4*>(&bs[cur][kk * 132 + tx * 4]);
            u64 a0 = *reinterpret_cast<const u64*>(&as2[cur][kk * 132 + ty * 8 + 0]);
            u64 a1 = *reinterpret_cast<const u64*>(&as2[cur][kk * 132 + ty * 8 + 2]);
            u64 a2 = *reinterpret_cast<const u64*>(&as2[cur][kk * 132 + ty * 8 + 4]);
            u64 a3 = *reinterpret_cast<const u64*>(&as2[cur][kk * 132 + ty * 8 + 6]);
            u64 bb0 = pack2(b.x, b.x), bb1 = pack2(b.y, b.y);
            u64 bb2 = pack2(b.z, b.z), bb3 = pack2(b.w, b.w);
            fma2(acc[0][0], a0, bb0); fma2(acc[0][1], a0, bb1);
            fma2(acc[0][2], a0, bb2); fma2(acc[0][3], a0, bb3);
            fma2(acc[1][0], a1, bb0); fma2(acc[1][1], a1, bb1);
            fma2(acc[1][2], a1, bb2); fma2(acc[1][3], a1, bb3);
            fma2(acc[2][0], a2, bb0); fma2(acc[2][1], a2, bb1);
            fma2(acc[2][2], a2, bb2); fma2(acc[2][3], a2, bb3);
            fma2(acc[3][0], a3, bb0); fma2(acc[3][1], a3, bb1);
            fma2(acc[3][2], a3, bb2); fma2(acc[3][3], a3, bb3);
        }
        if (kb < 7) { sts(cur ^ 1); __syncthreads(); }
    }

    float* up = g_up + ((size_t)(n * 32 + kc)) * C_ * C_;
#pragma unroll
    for (int p = 0; p < 4; p++) {
        int co0 = ty * 8 + 2 * p;
        float4 vl = make_float4(lo2(acc[p][0]), lo2(acc[p][1]),
                                lo2(acc[p][2]), lo2(acc[p][3]));
        float4 vh = make_float4(hi2(acc[p][0]), hi2(acc[p][1]),
                                hi2(acc[p][2]), hi2(acc[p][3]));
        *reinterpret_cast<float4*>(&up[co0 * 128 + tx * 4]) = vl;
        *reinterpret_cast<float4*>(&up[(co0 + 1) * 128 + tx * 4]) = vh;
    }
}

// K3b: reduce 32 split-K partials; write u transposed: g_u[n][ci][co]
__global__ void k3_red()
{
    int o = blockIdx.x * 256 + threadIdx.x;   // 131072
    int n = o >> 14, r = o & 16383;
    float s = 0.f;
#pragma unroll
    for (int kc = 0; kc < 32; kc++)
        s += g_up[(((size_t)(n * 32 + kc)) << 14) + r];
    int co = r >> 7, ci = r & 127;
    g_u[((size_t)n << 14) + ci * 128 + co] = s;
}

// ---------------------------------------------------------------------------
// K4: out = max( s3 * sum_ci u[n,co,ci]*t2[ci,p],  x[co,p] - 0.2*sum_jj t7 taps )
// double-buffered u chunks via cp.async; epilogue from smem t7 slab.
// ---------------------------------------------------------------------------
__global__ void k4_out(const float* __restrict__ x, const float* __restrict__ p1,
                       float* __restrict__ out)
{
    __shared__ __align__(16) float xs [128 * 64];     // t2[ci][w], later t7[co][w]
    __shared__ __align__(16) float as2[2][2048];      // u chunks [kk=ci][co]
    const int row = blockIdx.x, n = blockIdx.y;
    const int t = threadIdx.x;  // 128
    const int tx = t & 7, ty = t >> 3;
    const float* xn = x + (size_t)n * C_ * HW + row * 64;
    const float* un = g_u + ((size_t)n << 14);

#pragma unroll
    for (int r = 0; r < 4; r++)
        cpa16(s2u(&as2[0][r * 512 + t * 4]), &un[r * 512 + t * 4]);
    cpa_commit();

#pragma unroll
    for (int r = 0; r < 16; r++) {
        int idx4 = r * 512 + t * 4;
        int ci = idx4 >> 6, w = idx4 & 63;
        float s = 1.f + p1[ci * 64 + row];
        float4 v = *reinterpret_cast<const float4*>(&xn[(size_t)ci * HW + w]);
        v.x *= s; v.y *= s; v.z *= s; v.w *= s;
        *reinterpret_cast<float4*>(&xs[idx4]) = v;
    }

    u64 acc[4][8];
#pragma unroll
    for (int p = 0; p < 4; p++)
#pragma unroll
        for (int j = 0; j < 8; j++) acc[p][j] = 0ull;

    cpa_wait0();
    __syncthreads();

    for (int kb = 0; kb < 8; kb++) {
        const int cur = kb & 1;
        if (kb < 7) {
#pragma unroll
            for (int r = 0; r < 4; r++)
                cpa16(s2u(&as2[cur ^ 1][r * 512 + t * 4]),
                      &un[(kb + 1) * 2048 + r * 512 + t * 4]);
            cpa_commit();
        }
#pragma unroll
        for (int kk = 0; kk < 16; kk++) {
            int k = kb * 16 + kk;
            float4 b0 = *reinterpret_cast<const float4*>(&xs[k * 64 + tx * 8]);
            float4 b1 = *reinterpret_cast<const float4*>(&xs[k * 64 + tx * 8 + 4]);
            u64 a0 = *reinterpret_cast<const u64*>(&as2[cur][kk * 128 + ty * 8 + 0]);
            u64 a1 = *reinterpret_cast<const u64*>(&as2[cur][kk * 128 + ty * 8 + 2]);
            u64 a2 = *reinterpret_cast<const u64*>(&as2[cur][kk * 128 + ty * 8 + 4]);
            u64 a3 = *reinterpret_cast<const u64*>(&as2[cur][kk * 128 + ty * 8 + 6]);
            u64 bb[8];
            bb[0] = pack2(b0.x, b0.x); bb[1] = pack2(b0.y, b0.y);
            bb[2] = pack2(b0.z, b0.z); bb[3] = pack2(b0.w, b0.w);
            bb[4] = pack2(b1.x, b1.x); bb[5] = pack2(b1.y, b1.y);
            bb[6] = pack2(b1.z, b1.z); bb[7] = pack2(b1.w, b1.w);
#pragma unroll
            for (int j = 0; j < 8; j++) {
                fma2(acc[0][j], a0, bb[j]);
                fma2(acc[1][j], a1, bb[j]);
                fma2(acc[2][j], a2, bb[j]);
                fma2(acc[3][j], a3, bb[j]);
            }
        }
        if (kb < 7) { cpa_wait0(); __syncthreads(); }
    }

    // epilogue: reuse xs for t7[n,:,row,:]
    __syncthreads();
#pragma unroll
    for (int r = 0; r < 16; r++) {
        int idx4 = r * 512 + t * 4;
        int ci = idx4 >> 6, w = idx4 & 63;
        *reinterpret_cast<float4*>(&xs[idx4]) =
            *reinterpret_cast<const float4*>(
                &g_t7[((size_t)n * C_ + ci) * HW + row * 64 + w]);
    }
    __syncthreads();

    const float s3 = 0.01928793f;    // 1/sqrt(2688)
#pragma unroll
    for (int p = 0; p < 4; p++) {
#pragma unroll
        for (int half = 0; half < 2; half++) {
            int co = ty * 8 + 2 * p + half;
            const float* xr = xn + (size_t)co * HW;
            float4 xv0 = *reinterpret_cast<const float4*>(&xr[tx * 8]);
            float4 xv1 = *reinterpret_cast<const float4*>(&xr[tx * 8 + 4]);
            float xv[8] = {xv0.x, xv0.y, xv0.z, xv0.w, xv1.x, xv1.y, xv1.z, xv1.w};
            float res[8];
#pragma unroll
            for (int j = 0; j < 8; j++) {
                int pp = tx * 8 + j;
                float a = half ? hi2(acc[p][j]) : lo2(acc[p][j]);
                float sum = 0.f;
#pragma unroll
                for (int jj = 0; jj < 5; jj++) {
                    int wp = pp + 3 * jj - 6;
                    if ((unsigned)wp < 64u) sum += xs[co * 64 + wp];
                }
                float t12 = xv[j] - 0.2f * sum;
                res[j] = fmaxf(s3 * a, t12);
            }
            float* orow = out + ((size_t)n * C_ + co) * HW + row * 64;
            *reinterpret_cast<float4*>(&orow[tx * 8]) =
                make_float4(res[0], res[1], res[2], res[3]);
            *reinterpret_cast<float4*>(&orow[tx * 8 + 4]) =
                make_float4(res[4], res[5], res[6], res[7]);
        }
    }
}

// ---------------------------------------------------------------------------
extern "C" void kernel_launch(void* const* d_in, const int* in_sizes, int n_in,
                              void* d_out, int out_size)
{
    const float* x   = (const float*)d_in[0];   // (8,128,64,64)
    const float* p1w = (const float*)d_in[1];   // (1,128,64,1)
    const float* p7w = (const float*)d_in[2];   // (128,128)
    const float* p10 = (const float*)d_in[3];   // (2688,32)
    float* out = (float*)d_out;

    k0_tr  <<<64, 256>>>(p7w);
    k1_t7  <<<dim3(64, 8), 128>>>(x);
    k2_conv<<<dim3(16, 4, 8), 128>>>(x, p10);
    k3_part<<<dim3(32, 8), 512>>>(x, p1w);
    k3_red <<<512, 256>>>();
    k4_out <<<dim3(64, 8), 128>>>(x, p1w, out);
}